// round 11
// baseline (speedup 1.0000x reference)
#include <cuda_runtime.h>
#include <cuda_fp16.h>
#include <math.h>
#include <stdint.h>

// Glm4vMoeTextTopkRouter R9:
//  kernel 1: one-time split of weight into fp16 hi/lo swizzled chunk images (2 MB, L2-resident).
//  kernel 2: BM=64 x NE=128, 8 warps (m16n64), fp16 split mma.sync (HH->acc, HL+LH->cor),
//            smem fp32 sum flushed every 4 chunks; A single-buffered (2 bars/chunk),
//            B double-buffered via cp.async. regs<=128 + smem<=115.5KB => 2 CTAs/SM so
//            one CTA's MMA covers the other's staging barriers.

#define HD 4096
#define NE 128
#define TOPK 8
#define BM 64
#define KC 64
#define NCH (HD / KC)        // 64
#define NT 256               // 8 warps

#define LO_SCALE 2048.0f
#define LO_INV   (1.0f / 2048.0f)

#define SW128(o) ((uint32_t)(o) ^ ((((uint32_t)(o)) >> 3) & 0x70))

// B image: per chunk [hi 16KB][lo 16KB], expert-major rows of 128B
#define BIMG_CHUNK 32768
__device__ __align__(16) char gBconv[NCH * BIMG_CHUNK];   // 2 MB

// ---- dynamic smem layout ----
#define OFF_BIAS  0                        // 128 f32 (512B)
#define OFF_SUM   512                      // 64 x 129 f32 = 33024
#define OFF_A     (512 + 33024)            // 33536: A_hi 8K | A_lo 8K
#define A_MAT     8192
#define OFF_B     (OFF_A + 2 * A_MAT)      // 49920: double buffer of 32K (B_hi 16K | B_lo 16K)
#define B_MAT     16384
#define SMEM_TOTAL (OFF_B + 2 * BIMG_CHUNK)  // 115456

__device__ __forceinline__ uint32_t smem_u32(const void* p) {
    uint32_t a;
    asm("{ .reg .u64 t; cvta.to.shared.u64 t, %1; cvt.u32.u64 %0, t; }" : "=r"(a) : "l"(p));
    return a;
}

__device__ __forceinline__ void ldsm_x4(uint32_t addr, uint32_t* r) {
    asm volatile("ldmatrix.sync.aligned.m8n8.x4.shared.b16 {%0,%1,%2,%3}, [%4];"
                 : "=r"(r[0]), "=r"(r[1]), "=r"(r[2]), "=r"(r[3]) : "r"(addr));
}

__device__ __forceinline__ void mma16816(float* c, const uint32_t* a, uint32_t b0, uint32_t b1) {
    asm volatile("mma.sync.aligned.m16n8k16.row.col.f32.f16.f16.f32 "
                 "{%0,%1,%2,%3}, {%4,%5,%6,%7}, {%8,%9}, {%0,%1,%2,%3};"
                 : "+f"(c[0]), "+f"(c[1]), "+f"(c[2]), "+f"(c[3])
                 : "r"(a[0]), "r"(a[1]), "r"(a[2]), "r"(a[3]), "r"(b0), "r"(b1));
}

__device__ __forceinline__ void cp_async16(uint32_t smem_dst, const void* gsrc) {
    asm volatile("cp.async.cg.shared.global [%0], [%1], 16;"
                 :: "r"(smem_dst), "l"(gsrc) : "memory");
}
#define CP_COMMIT() asm volatile("cp.async.commit_group;" ::: "memory")
#define CP_WAIT0()  asm volatile("cp.async.wait_group 0;" ::: "memory")

__device__ __forceinline__ uint32_t h2u(half2 h) { return *reinterpret_cast<uint32_t*>(&h); }

__device__ __forceinline__ void store_split(char* hi_p, char* lo_p, float4 v) {
    half2 h0 = __floats2half2_rn(v.x, v.y);
    half2 h1 = __floats2half2_rn(v.z, v.w);
    float2 f0 = __half22float2(h0);
    float2 f1 = __half22float2(h1);
    half2 l0 = __floats2half2_rn((v.x - f0.x) * LO_SCALE, (v.y - f0.y) * LO_SCALE);
    half2 l1 = __floats2half2_rn((v.z - f1.x) * LO_SCALE, (v.w - f1.y) * LO_SCALE);
    *(uint2*)hi_p = make_uint2(h2u(h0), h2u(h1));
    *(uint2*)lo_p = make_uint2(h2u(l0), h2u(l1));
}

// verified ldmatrix address maps (128B pitch, SW128)
__device__ __forceinline__ uint32_t a_addr(uint32_t base, int l, int mb, int kb) {
    int row = mb + (l & 7) + ((l >> 3) & 1) * 8;
    int colb = (kb + ((l >> 4) << 3)) * 2;
    return base + SW128(row * 128 + colb);
}
__device__ __forceinline__ uint32_t b_addr(uint32_t base, int l, int nb, int kb) {
    int row = nb + (l & 7) + ((l >> 4) << 3);
    int colb = (kb + (((l >> 3) & 1) << 3)) * 2;
    return base + SW128(row * 128 + colb);
}

// ---- kernel 1: build B image ----
__global__ void prep_b_kernel(const float* __restrict__ weight) {
    const int e = blockIdx.x;
    const int k = threadIdx.x * 4;
    float4 v = *(const float4*)(weight + (size_t)e * HD + k);
    const int chunk = k >> 6;
    const int col = k & 63;
    uint32_t off = SW128((uint32_t)(e * 128 + col * 2));
    char* base = gBconv + (size_t)chunk * BIMG_CHUNK;
    store_split(base + off, base + 16384 + off, v);
}

// ---- kernel 2: main fused router ----
__global__ __launch_bounds__(NT, 2)
void router_mma_kernel(const float* __restrict__ hidden,
                       const float* __restrict__ bias,
                       float* __restrict__ out, int T)
{
    extern __shared__ char smem[];
    const uint32_t sbase = smem_u32(smem);
    const int tid = threadIdx.x;
    const int wid = tid >> 5, lid = tid & 31;
    const int m0 = blockIdx.x * BM;

    float* sumsm = (float*)(smem + OFF_SUM);
    if (tid < NE) ((float*)(smem + OFF_BIAS))[tid] = bias[tid];
    for (int i = tid; i < BM * 129; i += NT) sumsm[i] = 0.0f;

    const int arow = tid >> 4;   // 0..15
    const int c4   = tid & 15;
    const float* aBase = hidden + (size_t)(m0 + arow) * HD + c4 * 4;

    // warp grid 4m x 2n; warp tile m16 x n64
    const int mb = (wid >> 1) * 16;
    const int nb = (wid & 1) * 64;

    // frag f = ng*2 + r  (ng: n16 group 0..3, r: n8 half)
    float acc[8][4], cor[8][4];
#pragma unroll
    for (int f = 0; f < 8; f++)
#pragma unroll
        for (int q = 0; q < 4; q++) { acc[f][q] = 0.0f; cor[f][q] = 0.0f; }

    float4 va[4];
#pragma unroll
    for (int i = 0; i < 4; i++) va[i] = *(const float4*)(aBase + (size_t)(i * 16) * HD);

    // prologue: B chunk 0
    {
        uint32_t dst = sbase + OFF_B + tid * 128;
        const char* src = gBconv + (size_t)tid * 128;
#pragma unroll
        for (int i = 0; i < 8; i++) cp_async16(dst + i * 16, src + i * 16);
        CP_COMMIT();
    }

    for (int c = 0; c < NCH; ++c) {
        __syncthreads();   // bar1: all warps retired their LDSM-A reads of chunk c-1
        // STS A(c) hi/lo into the single A buffer
        char* stgA = smem + OFF_A;
#pragma unroll
        for (int i = 0; i < 4; i++) {
            uint32_t off = SW128((uint32_t)((i * 16 + arow) * 128 + c4 * 8));
            store_split(stgA + off, stgA + A_MAT + off, va[i]);
        }
        // LDG A(c+1) (latency overlapped by bar2 + mma)
        if (c + 1 < NCH) {
            const float* ap = aBase + (size_t)(c + 1) * KC;
#pragma unroll
            for (int i = 0; i < 4; i++) va[i] = *(const float4*)(ap + (size_t)(i * 16) * HD);
        }
        CP_WAIT0();        // B(c) landed (only group in flight)
        __syncthreads();   // bar2: A(c)+B(c) visible CTA-wide

        // issue B(c+1) into the other buffer (its readers, mma(c-1), retired before bar1)
        if (c + 1 < NCH) {
            uint32_t dst = sbase + OFF_B + ((c + 1) & 1) * BIMG_CHUNK + tid * 128;
            const char* src = gBconv + (size_t)(c + 1) * BIMG_CHUNK + (size_t)tid * 128;
#pragma unroll
            for (int i = 0; i < 8; i++) cp_async16(dst + i * 16, src + i * 16);
            CP_COMMIT();
        }

        const uint32_t sA_hi = sbase + OFF_A;
        const uint32_t sA_lo = sA_hi + A_MAT;
        const uint32_t sB_hi = sbase + OFF_B + (c & 1) * BIMG_CHUNK;
        const uint32_t sB_lo = sB_hi + B_MAT;

#pragma unroll
        for (int ks = 0; ks < 4; ks++) {
            const int kb = ks * 16;
            uint32_t ah[4], al[4], bh[4][4];
            ldsm_x4(a_addr(sA_hi, lid, mb, kb), ah);
            ldsm_x4(a_addr(sA_lo, lid, mb, kb), al);
#pragma unroll
            for (int ng = 0; ng < 4; ng++) {
                uint32_t bl[4];
                ldsm_x4(b_addr(sB_hi, lid, nb + ng * 16, kb), bh[ng]);
                ldsm_x4(b_addr(sB_lo, lid, nb + ng * 16, kb), bl);
                mma16816(acc[ng * 2 + 0], ah, bh[ng][0], bh[ng][1]);   // HH
                mma16816(acc[ng * 2 + 1], ah, bh[ng][2], bh[ng][3]);
                mma16816(cor[ng * 2 + 0], ah, bl[0], bl[1]);           // HL
                mma16816(cor[ng * 2 + 1], ah, bl[2], bl[3]);
            }
#pragma unroll
            for (int ng = 0; ng < 4; ng++) {                           // LH (spaced from HL)
                mma16816(cor[ng * 2 + 0], al, bh[ng][0], bh[ng][1]);
                mma16816(cor[ng * 2 + 1], al, bh[ng][2], bh[ng][3]);
            }
        }

        // flush TC accumulators into smem fp32 sum every 4 chunks (breaks TC C-add chain)
        if ((c & 3) == 3) {
#pragma unroll
            for (int ng = 0; ng < 4; ng++)
#pragma unroll
                for (int r = 0; r < 2; r++) {
                    const int f = ng * 2 + r;
#pragma unroll
                    for (int q = 0; q < 4; q++) {
                        const int row = mb + (lid >> 2) + (q >> 1) * 8;
                        const int col = nb + ng * 16 + r * 8 + (lid & 3) * 2 + (q & 1);
                        sumsm[row * 129 + col] += fmaf(cor[f][q], LO_INV, acc[f][q]);
                        acc[f][q] = 0.0f; cor[f][q] = 0.0f;
                    }
                }
        }
    }

    __syncthreads();

    // sigmoid in place
    for (int idx = tid; idx < BM * NE; idx += NT) {
        const int row = idx >> 7, col = idx & 127;
        float v = sumsm[row * 129 + col];
        sumsm[row * 129 + col] = 1.0f / (1.0f + expf(-v));
    }
    __syncthreads();

    // top-8 per token (threads 0..63); strict '>' => lowest-index ties like lax.top_k
    if (tid < BM) {
        const int gtok = m0 + tid;
        float* row = sumsm + tid * 129;
        const float* sb = (const float*)(smem + OFF_BIAS);
        float w[TOPK]; int idx[TOPK]; float ssum = 0.0f;
#pragma unroll
        for (int p = 0; p < TOPK; p++) {
            float mx = -1e30f; int mi = 0;
#pragma unroll 16
            for (int e = 0; e < NE; e++) {
                float v = row[e] + sb[e];
                if (v > mx) { mx = v; mi = e; }
            }
            idx[p] = mi;
            w[p] = row[mi];
            row[mi] = -3e30f;
            ssum += w[p];
        }
        const float inv = 1.0f / (ssum + 1e-20f);
        float* oi = out + (size_t)gtok * TOPK;
        float* ow = out + (size_t)T * TOPK + (size_t)gtok * TOPK;
#pragma unroll
        for (int p = 0; p < TOPK; p++) {
            oi[p] = (float)idx[p];
            ow[p] = w[p] * inv;
        }
    }
}

extern "C" void kernel_launch(void* const* d_in, const int* in_sizes, int n_in,
                              void* d_out, int out_size)
{
    const float* hidden = (const float*)d_in[0];
    const float* weight = (const float*)d_in[1];
    const float* bias   = (const float*)d_in[2];
    const int T = in_sizes[0] / HD;   // 32768

    prep_b_kernel<<<NE, HD / 4>>>(weight);

    cudaFuncSetAttribute(router_mma_kernel,
                         cudaFuncAttributeMaxDynamicSharedMemorySize, SMEM_TOTAL);
    router_mma_kernel<<<T / BM, NT, SMEM_TOTAL>>>(hidden, bias, (float*)d_out, T);
}

// round 13
// speedup vs baseline: 1.5358x; 1.5358x over previous
#include <cuda_runtime.h>
#include <cuda_fp16.h>
#include <math.h>
#include <stdint.h>

// Glm4vMoeTextTopkRouter R12:
//  kernel 1: one-time split of weight into fp16 hi/lo swizzled chunk images (2 MB, L2-resident).
//  kernel 2: BM=128 x NE=128, NT=512 (16 warps, m16n64 tiles -> low regs), fp16 split
//            mma.sync (HH->acc, HL+LH->cor), smem fp32 sum flushed every 4 chunks,
//            A dbuf STS + B dbuf cp.async from image, ONE barrier per chunk,
//            fused sigmoid + bias top-8 + normalize.

#define HD 4096
#define NE 128
#define TOPK 8
#define BM 128
#define KC 64
#define NCH (HD / KC)        // 64
#define NT 512               // 16 warps

#define LO_SCALE 2048.0f
#define LO_INV   (1.0f / 2048.0f)

#define SW128(o) ((uint32_t)(o) ^ ((((uint32_t)(o)) >> 3) & 0x70))

// B image: per chunk [hi 16KB][lo 16KB], expert-major rows of 128B
#define BIMG_CHUNK 32768
__device__ __align__(16) char gBconv[NCH * BIMG_CHUNK];   // 2 MB

// ---- dynamic smem layout ----
#define OFF_BIAS  0                         // 128 f32
#define OFF_SUM   512                       // 128 x 129 f32 = 66048
#define OFF_A     (512 + 66048)             // 66560: dbuf of (A_hi 16K | A_lo 16K)
#define A_MAT     16384
#define OFF_B     (OFF_A + 2 * 2 * A_MAT)   // 132096: dbuf of (B_hi 16K | B_lo 16K)
#define B_MAT     16384
#define SMEM_TOTAL (OFF_B + 2 * BIMG_CHUNK) // 197632

__device__ __forceinline__ uint32_t smem_u32(const void* p) {
    uint32_t a;
    asm("{ .reg .u64 t; cvta.to.shared.u64 t, %1; cvt.u32.u64 %0, t; }" : "=r"(a) : "l"(p));
    return a;
}

__device__ __forceinline__ void ldsm_x4(uint32_t addr, uint32_t* r) {
    asm volatile("ldmatrix.sync.aligned.m8n8.x4.shared.b16 {%0,%1,%2,%3}, [%4];"
                 : "=r"(r[0]), "=r"(r[1]), "=r"(r[2]), "=r"(r[3]) : "r"(addr));
}

__device__ __forceinline__ void mma16816(float* c, const uint32_t* a, uint32_t b0, uint32_t b1) {
    asm volatile("mma.sync.aligned.m16n8k16.row.col.f32.f16.f16.f32 "
                 "{%0,%1,%2,%3}, {%4,%5,%6,%7}, {%8,%9}, {%0,%1,%2,%3};"
                 : "+f"(c[0]), "+f"(c[1]), "+f"(c[2]), "+f"(c[3])
                 : "r"(a[0]), "r"(a[1]), "r"(a[2]), "r"(a[3]), "r"(b0), "r"(b1));
}

__device__ __forceinline__ void cp_async16(uint32_t smem_dst, const void* gsrc) {
    asm volatile("cp.async.cg.shared.global [%0], [%1], 16;"
                 :: "r"(smem_dst), "l"(gsrc) : "memory");
}
#define CP_COMMIT() asm volatile("cp.async.commit_group;" ::: "memory")
#define CP_WAIT0()  asm volatile("cp.async.wait_group 0;" ::: "memory")

__device__ __forceinline__ uint32_t h2u(half2 h) { return *reinterpret_cast<uint32_t*>(&h); }

__device__ __forceinline__ void store_split(char* hi_p, char* lo_p, float4 v) {
    half2 h0 = __floats2half2_rn(v.x, v.y);
    half2 h1 = __floats2half2_rn(v.z, v.w);
    float2 f0 = __half22float2(h0);
    float2 f1 = __half22float2(h1);
    half2 l0 = __floats2half2_rn((v.x - f0.x) * LO_SCALE, (v.y - f0.y) * LO_SCALE);
    half2 l1 = __floats2half2_rn((v.z - f1.x) * LO_SCALE, (v.w - f1.y) * LO_SCALE);
    *(uint2*)hi_p = make_uint2(h2u(h0), h2u(h1));
    *(uint2*)lo_p = make_uint2(h2u(l0), h2u(l1));
}

// verified ldmatrix address maps (128B pitch, SW128)
__device__ __forceinline__ uint32_t a_addr(uint32_t base, int l, int mb, int kb) {
    int row = mb + (l & 7) + ((l >> 3) & 1) * 8;
    int colb = (kb + ((l >> 4) << 3)) * 2;
    return base + SW128(row * 128 + colb);
}
__device__ __forceinline__ uint32_t b_addr(uint32_t base, int l, int nb, int kb) {
    int row = nb + (l & 7) + ((l >> 4) << 3);
    int colb = (kb + (((l >> 3) & 1) << 3)) * 2;
    return base + SW128(row * 128 + colb);
}

// ---- kernel 1: build B image ----
__global__ void prep_b_kernel(const float* __restrict__ weight) {
    const int e = blockIdx.x;
    const int k = threadIdx.x * 4;
    float4 v = *(const float4*)(weight + (size_t)e * HD + k);
    const int chunk = k >> 6;
    const int col = k & 63;
    uint32_t off = SW128((uint32_t)(e * 128 + col * 2));
    char* base = gBconv + (size_t)chunk * BIMG_CHUNK;
    store_split(base + off, base + 16384 + off, v);
}

// ---- kernel 2: main fused router ----
__global__ __launch_bounds__(NT, 1)
void router_mma_kernel(const float* __restrict__ hidden,
                       const float* __restrict__ bias,
                       float* __restrict__ out, int T)
{
    extern __shared__ char smem[];
    const uint32_t sbase = smem_u32(smem);
    const int tid = threadIdx.x;
    const int wid = tid >> 5, lid = tid & 31;
    const int m0 = blockIdx.x * BM;

    float* sumsm = (float*)(smem + OFF_SUM);
    if (tid < NE) ((float*)(smem + OFF_BIAS))[tid] = bias[tid];
    for (int i = tid; i < BM * 129; i += NT) sumsm[i] = 0.0f;

    const int arow = tid >> 4;   // 0..31
    const int c4   = tid & 15;
    const float* aBase = hidden + (size_t)(m0 + arow) * HD + c4 * 4;

    // warp grid 8m x 2n; warp tile m16 x n64
    const int mb = (wid >> 1) * 16;
    const int nb = (wid & 1) * 64;

    // frag f = ng*2 + r  (ng: n16 group 0..3, r: n8 half)
    float acc[8][4], cor[8][4];
#pragma unroll
    for (int f = 0; f < 8; f++)
#pragma unroll
        for (int q = 0; q < 4; q++) { acc[f][q] = 0.0f; cor[f][q] = 0.0f; }

    float4 va[4];
#pragma unroll
    for (int i = 0; i < 4; i++) va[i] = *(const float4*)(aBase + (size_t)(i * 32) * HD);

    // prologue: B chunk 0 (64B per thread, linear copy of pre-swizzled image)
    {
        uint32_t dst = sbase + OFF_B + tid * 64;
        const char* src = gBconv + (size_t)tid * 64;
#pragma unroll
        for (int i = 0; i < 4; i++) cp_async16(dst + i * 16, src + i * 16);
        CP_COMMIT();
    }

    for (int c = 0; c < NCH; ++c) {
        char* stgA = smem + OFF_A + (c & 1) * 2 * A_MAT;
        // STS A(c) hi/lo (buf c&1; its readers were chunk c-2, retired before bar(c-1))
#pragma unroll
        for (int i = 0; i < 4; i++) {
            uint32_t off = SW128((uint32_t)((i * 32 + arow) * 128 + c4 * 8));
            store_split(stgA + off, stgA + A_MAT + off, va[i]);
        }
        // LDG A(c+1): latency hidden under bar + mma(c)
        if (c + 1 < NCH) {
            const float* ap = aBase + (size_t)(c + 1) * KC;
#pragma unroll
            for (int i = 0; i < 4; i++) va[i] = *(const float4*)(ap + (size_t)(i * 32) * HD);
        }
        CP_WAIT0();        // B(c) landed (single group in flight)
        __syncthreads();   // A(c)+B(c) visible; mma(c-1) retired CTA-wide

        // issue B(c+1) into the other buffer (readers = mma(c-1), retired)
        if (c + 1 < NCH) {
            uint32_t dst = sbase + OFF_B + ((c + 1) & 1) * BIMG_CHUNK + tid * 64;
            const char* src = gBconv + (size_t)(c + 1) * BIMG_CHUNK + (size_t)tid * 64;
#pragma unroll
            for (int i = 0; i < 4; i++) cp_async16(dst + i * 16, src + i * 16);
            CP_COMMIT();
        }

        const uint32_t sA_hi = sbase + OFF_A + (c & 1) * 2 * A_MAT;
        const uint32_t sA_lo = sA_hi + A_MAT;
        const uint32_t sB_hi = sbase + OFF_B + (c & 1) * BIMG_CHUNK;
        const uint32_t sB_lo = sB_hi + B_MAT;

#pragma unroll
        for (int ks = 0; ks < 4; ks++) {
            const int kb = ks * 16;
            uint32_t ah[4], al[4], bh[4][4];
            ldsm_x4(a_addr(sA_hi, lid, mb, kb), ah);
            ldsm_x4(a_addr(sA_lo, lid, mb, kb), al);
#pragma unroll
            for (int ng = 0; ng < 4; ng++) {
                uint32_t bl[4];
                ldsm_x4(b_addr(sB_hi, lid, nb + ng * 16, kb), bh[ng]);
                ldsm_x4(b_addr(sB_lo, lid, nb + ng * 16, kb), bl);
                mma16816(acc[ng * 2 + 0], ah, bh[ng][0], bh[ng][1]);   // HH
                mma16816(acc[ng * 2 + 1], ah, bh[ng][2], bh[ng][3]);
                mma16816(cor[ng * 2 + 0], ah, bl[0], bl[1]);           // HL
                mma16816(cor[ng * 2 + 1], ah, bl[2], bl[3]);
            }
#pragma unroll
            for (int ng = 0; ng < 4; ng++) {                           // LH (spaced from HL)
                mma16816(cor[ng * 2 + 0], al, bh[ng][0], bh[ng][1]);
                mma16816(cor[ng * 2 + 1], al, bh[ng][2], bh[ng][3]);
            }
        }

        // flush TC accumulators into smem fp32 sum every 4 chunks (breaks TC C-add chain)
        if ((c & 3) == 3) {
#pragma unroll
            for (int ng = 0; ng < 4; ng++)
#pragma unroll
                for (int r = 0; r < 2; r++) {
                    const int f = ng * 2 + r;
#pragma unroll
                    for (int q = 0; q < 4; q++) {
                        const int row = mb + (lid >> 2) + (q >> 1) * 8;
                        const int col = nb + ng * 16 + r * 8 + (lid & 3) * 2 + (q & 1);
                        sumsm[row * 129 + col] += fmaf(cor[f][q], LO_INV, acc[f][q]);
                        acc[f][q] = 0.0f; cor[f][q] = 0.0f;
                    }
                }
        }
    }

    __syncthreads();

    // sigmoid in place
    for (int idx = tid; idx < BM * NE; idx += NT) {
        const int row = idx >> 7, col = idx & 127;
        float v = sumsm[row * 129 + col];
        sumsm[row * 129 + col] = 1.0f / (1.0f + expf(-v));
    }
    __syncthreads();

    // top-8 per token (threads 0..127); strict '>' => lowest-index ties like lax.top_k
    if (tid < BM) {
        const int gtok = m0 + tid;
        float* row = sumsm + tid * 129;
        const float* sb = (const float*)(smem + OFF_BIAS);
        float w[TOPK]; int idx[TOPK]; float ssum = 0.0f;
#pragma unroll
        for (int p = 0; p < TOPK; p++) {
            float mx = -1e30f; int mi = 0;
#pragma unroll 16
            for (int e = 0; e < NE; e++) {
                float v = row[e] + sb[e];
                if (v > mx) { mx = v; mi = e; }
            }
            idx[p] = mi;
            w[p] = row[mi];
            row[mi] = -3e30f;
            ssum += w[p];
        }
        const float inv = 1.0f / (ssum + 1e-20f);
        float* oi = out + (size_t)gtok * TOPK;
        float* ow = out + (size_t)T * TOPK + (size_t)gtok * TOPK;
#pragma unroll
        for (int p = 0; p < TOPK; p++) {
            oi[p] = (float)idx[p];
            ow[p] = w[p] * inv;
        }
    }
}

extern "C" void kernel_launch(void* const* d_in, const int* in_sizes, int n_in,
                              void* d_out, int out_size)
{
    const float* hidden = (const float*)d_in[0];
    const float* weight = (const float*)d_in[1];
    const float* bias   = (const float*)d_in[2];
    const int T = in_sizes[0] / HD;   // 32768

    prep_b_kernel<<<NE, HD / 4>>>(weight);

    cudaFuncSetAttribute(router_mma_kernel,
                         cudaFuncAttributeMaxDynamicSharedMemorySize, SMEM_TOTAL);
    router_mma_kernel<<<T / BM, NT, SMEM_TOTAL>>>(hidden, bias, (float*)d_out, T);
}